// round 8
// baseline (speedup 1.0000x reference)
#include <cuda_runtime.h>
#include <math.h>

#define NLEV   16
#define TSZ    524288
#define HIDDEN 64
#define FEAT   13
#define DIN    35
#define MAXN   1048576
#define NBUCK  32768

typedef unsigned long long u64;

__device__ __forceinline__ u64 pack2(float lo, float hi) {
    u64 r; asm("mov.b64 %0, {%1, %2};" : "=l"(r) : "f"(lo), "f"(hi)); return r;
}
__device__ __forceinline__ u64 bcast2(float v) { return pack2(v, v); }
__device__ __forceinline__ u64 fma2(u64 a, u64 b, u64 c) {
    u64 d; asm("fma.rn.f32x2 %0, %1, %2, %3;" : "=l"(d) : "l"(a), "l"(b), "l"(c)); return d;
}
__device__ __forceinline__ void unpack2(u64 v, float& lo, float& hi) {
    asm("mov.b64 {%0, %1}, %2;" : "=f"(lo), "=f"(hi) : "l"(v));
}

// ---------------------------------------------------------------------------
// Weight staging + packed forms
// ---------------------------------------------------------------------------
__device__ float g_W0T[DIN][HIDDEN];
__device__ float g_W1T[HIDDEN][HIDDEN];
__device__ float g_W2T[HIDDEN][16];
__device__ float g_b0[HIDDEN];
__device__ float g_b1[HIDDEN];
__device__ float g_b2[16];

__device__ ulonglong2 g_W0p[DIN][16];
__device__ ulonglong2 g_W1p[HIDDEN][16];
__device__ ulonglong2 g_W2p[HIDDEN][4];
__device__ ulonglong2 g_b0p[16];
__device__ ulonglong2 g_b1p[16];
__device__ ulonglong2 g_b2p[4];

// ---------------------------------------------------------------------------
// Morton-sort scratch + encode staging
// ---------------------------------------------------------------------------
__device__ int   g_hist[NBUCK];
__device__ int   g_off[NBUCK];
__device__ int   g_cell[MAXN];
__device__ int   g_perm[MAXN];        // sorted slot -> original point id
__device__ float g_pts[MAXN * 3];     // points in sorted order
__device__ float2 g_enc[NLEV][MAXN];  // per-level features, sorted order

__global__ void prep_kernel(const float* __restrict__ V0, const float* __restrict__ g0, const float* __restrict__ b0,
                            const float* __restrict__ V1, const float* __restrict__ g1, const float* __restrict__ b1,
                            const float* __restrict__ V2, const float* __restrict__ g2, const float* __restrict__ b2)
{
    int o = threadIdx.x;
    if (o < HIDDEN) {
        float s = 0.f;
        for (int i = 0; i < DIN; i++) { float v = V0[o * DIN + i]; s += v * v; }
        float sc = g0[o] / sqrtf(s);
        for (int i = 0; i < DIN; i++) g_W0T[i][o] = V0[o * DIN + i] * sc;
        g_b0[o] = b0[o];

        s = 0.f;
        for (int i = 0; i < HIDDEN; i++) { float v = V1[o * HIDDEN + i]; s += v * v; }
        sc = g1[o] / sqrtf(s);
        for (int i = 0; i < HIDDEN; i++) g_W1T[i][o] = V1[o * HIDDEN + i] * sc;
        g_b1[o] = b1[o];
    }
    if (o < 16) {
        if (o < FEAT) {
            float s = 0.f;
            for (int i = 0; i < HIDDEN; i++) { float v = V2[o * HIDDEN + i]; s += v * v; }
            float sc = g2[o] / sqrtf(s);
            for (int i = 0; i < HIDDEN; i++) g_W2T[i][o] = V2[o * HIDDEN + i] * sc;
            g_b2[o] = b2[o];
        } else {
            for (int i = 0; i < HIDDEN; i++) g_W2T[i][o] = 0.f;
            g_b2[o] = 0.f;
        }
    }
}

__device__ __forceinline__ ulonglong2 pack4(const float* s) {
    ulonglong2 v;
    v.x = ((u64)__float_as_uint(s[1]) << 32) | (u64)__float_as_uint(s[0]);
    v.y = ((u64)__float_as_uint(s[3]) << 32) | (u64)__float_as_uint(s[2]);
    return v;
}

__global__ void pack_kernel()
{
    const int NW0 = DIN * 16, NW1 = HIDDEN * 16, NW2 = HIDDEN * 4;
    const int total = NW0 + NW1 + NW2 + 16 + 16 + 4;
    for (int e = threadIdx.x; e < total; e += blockDim.x) {
        int r = e;
        if (r < NW0) { (&g_W0p[0][0])[r] = pack4(&(&g_W0T[0][0])[4 * r]); continue; }
        r -= NW0;
        if (r < NW1) { (&g_W1p[0][0])[r] = pack4(&(&g_W1T[0][0])[4 * r]); continue; }
        r -= NW1;
        if (r < NW2) { (&g_W2p[0][0])[r] = pack4(&(&g_W2T[0][0])[4 * r]); continue; }
        r -= NW2;
        if (r < 16) { g_b0p[r] = pack4(&g_b0[4 * r]); continue; }
        r -= 16;
        if (r < 16) { g_b1p[r] = pack4(&g_b1[4 * r]); continue; }
        r -= 16;
        g_b2p[r] = pack4(&g_b2[4 * r]);
    }
}

// ---------------------------------------------------------------------------
// Morton counting sort
// ---------------------------------------------------------------------------
__global__ void zero_hist_kernel()
{
    int i = blockIdx.x * blockDim.x + threadIdx.x;
    if (i < NBUCK) g_hist[i] = 0;
}

__device__ __forceinline__ unsigned expand5(unsigned v)
{
    unsigned r = 0;
    #pragma unroll
    for (int b = 0; b < 5; b++) r |= ((v >> b) & 1u) << (3 * b);
    return r;
}

__global__ void assign_kernel(const float* __restrict__ points, int n)
{
    int i = blockIdx.x * blockDim.x + threadIdx.x;
    if (i >= n) return;
    const float ux = fminf(fmaxf((points[3 * i + 0] + 1.f) * 0.5f, 0.f), 1.f);
    const float uy = fminf(fmaxf((points[3 * i + 1] + 1.f) * 0.5f, 0.f), 1.f);
    const float uz = fminf(fmaxf((points[3 * i + 2] + 1.f) * 0.5f, 0.f), 1.f);
    const unsigned cx = min(31, (int)(ux * 32.f));
    const unsigned cy = min(31, (int)(uy * 32.f));
    const unsigned cz = min(31, (int)(uz * 32.f));
    const int key = (int)(expand5(cx) | (expand5(cy) << 1) | (expand5(cz) << 2));
    g_cell[i] = key;
    atomicAdd(&g_hist[key], 1);
}

__global__ void scan_kernel()
{
    __shared__ int part[256];
    const int t = threadIdx.x;
    int s = 0;
    for (int k = 0; k < 128; k++) s += g_hist[t * 128 + k];
    part[t] = s;
    __syncthreads();
    if (t == 0) {
        int run = 0;
        for (int j = 0; j < 256; j++) { int tmp = part[j]; part[j] = run; run += tmp; }
    }
    __syncthreads();
    int base = part[t];
    for (int k = 0; k < 128; k++) {
        int c = t * 128 + k;
        int v = g_hist[c];
        g_off[c] = base;
        base += v;
    }
}

__global__ void scatter_kernel(const float* __restrict__ points, int n)
{
    int i = blockIdx.x * blockDim.x + threadIdx.x;
    if (i >= n) return;
    const int key = g_cell[i];
    const int dst = atomicAdd(&g_off[key], 1);
    g_perm[dst] = i;
    g_pts[3 * dst + 0] = points[3 * i + 0];
    g_pts[3 * dst + 1] = points[3 * i + 1];
    g_pts[3 * dst + 2] = points[3 * i + 2];
}

struct GridParams { int gs[NLEV]; };

__device__ __forceinline__ float softplus100(float z)
{
    float x = 100.f * z;
    return (fmaxf(x, 0.f) + log1pf(__expf(-fabsf(x)))) * 0.01f;
}

// Corner order: c = i*4 + j*2 + k (matches reference OFFSETS loop nest).
__device__ __forceinline__ void level_setup(int gs, float ux, float uy, float uz,
                                            unsigned idxs[8], float& wx, float& wy, float& wz)
{
    const float gm1 = (float)(gs - 1);
    const float fx = ux * gm1, fy = uy * gm1, fz = uz * gm1;
    int ix = (int)floorf(fx); ix = min(max(ix, 0), gs - 2);
    int iy = (int)floorf(fy); iy = min(max(iy, 0), gs - 2);
    int iz = (int)floorf(fz); iz = min(max(iz, 0), gs - 2);
    wx = fx - (float)ix;
    wy = fy - (float)iy;
    wz = fz - (float)iz;

    if ((long long)gs * gs * gs <= (long long)TSZ) {
        const int g1 = gs, g2 = gs * gs;
        const int base = ix + g1 * iy + g2 * iz;
        idxs[0] = base;
        idxs[1] = base + g2;
        idxs[2] = base + g1;
        idxs[3] = base + g1 + g2;
        idxs[4] = base + 1;
        idxs[5] = base + 1 + g2;
        idxs[6] = base + 1 + g1;
        idxs[7] = base + 1 + g1 + g2;
    } else {
        const unsigned hx0 = (unsigned)ix,               hx1 = hx0 + 1u;
        const unsigned hy0 = (unsigned)iy * 2654435761u, hy1 = hy0 + 2654435761u;
        const unsigned hz0 = (unsigned)iz * 805459861u,  hz1 = hz0 + 805459861u;
        const unsigned M = (unsigned)(TSZ - 1);
        idxs[0] = (hx0 ^ hy0 ^ hz0) & M;
        idxs[1] = (hx0 ^ hy0 ^ hz1) & M;
        idxs[2] = (hx0 ^ hy1 ^ hz0) & M;
        idxs[3] = (hx0 ^ hy1 ^ hz1) & M;
        idxs[4] = (hx1 ^ hy0 ^ hz0) & M;
        idxs[5] = (hx1 ^ hy0 ^ hz1) & M;
        idxs[6] = (hx1 ^ hy1 ^ hz0) & M;
        idxs[7] = (hx1 ^ hy1 ^ hz1) & M;
    }
}

// ---------------------------------------------------------------------------
// Encode kernel: gathers only, high occupancy
// ---------------------------------------------------------------------------
__global__ __launch_bounds__(256, 5)
void encode_kernel(const float* __restrict__ table, int n, GridParams gp)
{
    const int s = blockIdx.x * 256 + threadIdx.x;
    if (s >= n) return;

    const float ux = fminf(fmaxf((g_pts[3 * s + 0] + 1.f) * 0.5f, 0.f), 1.f);
    const float uy = fminf(fmaxf((g_pts[3 * s + 1] + 1.f) * 0.5f, 0.f), 1.f);
    const float uz = fminf(fmaxf((g_pts[3 * s + 2] + 1.f) * 0.5f, 0.f), 1.f);

    const float2* __restrict__ tab = (const float2*)table;

    #pragma unroll 1
    for (int lv = 0; lv < NLEV; lv++) {
        unsigned idxs[8];
        float wx, wy, wz;
        level_setup(gp.gs[lv], ux, uy, uz, idxs, wx, wy, wz);
        const float2* __restrict__ tb = tab + (size_t)lv * TSZ;
        float2 f[8];
        #pragma unroll
        for (int c = 0; c < 8; c++) f[c] = __ldg(&tb[idxs[c]]);

        const float ox = 1.f - wx, oy = 1.f - wy, oz = 1.f - wz;
        const float w0 = ox * oy * oz,  w1 = ox * oy * wz;
        const float w2 = ox * wy * oz,  w3 = ox * wy * wz;
        const float w4 = wx * oy * oz,  w5 = wx * oy * wz;
        const float w6 = wx * wy * oz,  w7 = wx * wy * wz;
        float2 e;
        e.x = f[0].x * w0 + f[1].x * w1 + f[2].x * w2 + f[3].x * w3
            + f[4].x * w4 + f[5].x * w5 + f[6].x * w6 + f[7].x * w7;
        e.y = f[0].y * w0 + f[1].y * w1 + f[2].y * w2 + f[3].y * w3
            + f[4].y * w4 + f[5].y * w5 + f[6].y * w6 + f[7].y * w7;
        g_enc[lv][s] = e;
    }
}

// ---------------------------------------------------------------------------
// MLP kernel: pure FMA from shared weights + staged features
// ---------------------------------------------------------------------------
__global__ __launch_bounds__(128, 4)
void mlp_kernel(float* __restrict__ out, int n)
{
    __shared__ ulonglong2 sW0[DIN][16];
    __shared__ ulonglong2 sW1[HIDDEN][16];
    __shared__ ulonglong2 sW2[HIDDEN][4];
    __shared__ ulonglong2 sb0[16];
    __shared__ ulonglong2 sb1[16];
    __shared__ ulonglong2 sb2[4];

    const int tid = threadIdx.x;
    for (int i = tid; i < DIN * 16;    i += 128) (&sW0[0][0])[i] = (&g_W0p[0][0])[i];
    for (int i = tid; i < HIDDEN * 16; i += 128) (&sW1[0][0])[i] = (&g_W1p[0][0])[i];
    for (int i = tid; i < HIDDEN * 4;  i += 128) (&sW2[0][0])[i] = (&g_W2p[0][0])[i];
    if (tid < 16) { sb0[tid] = g_b0p[tid]; sb1[tid] = g_b1p[tid]; }
    if (tid < 4)  { sb2[tid] = g_b2p[tid]; }
    __syncthreads();

    const int s = blockIdx.x * 128 + tid;
    if (s >= n) return;
    const int p = g_perm[s];

    const float px = g_pts[3 * s + 0];
    const float py = g_pts[3 * s + 1];
    const float pz = g_pts[3 * s + 2];

    // Load all staged features up front (independent, coalesced)
    float2 e[NLEV];
    #pragma unroll
    for (int lv = 0; lv < NLEV; lv++) e[lv] = g_enc[lv][s];

    // ---- layer 0 --------------------------------------------------------
    u64 acc[32];
    #pragma unroll
    for (int q = 0; q < 16; q++) {
        const ulonglong2 b = sb0[q];
        acc[2 * q] = b.x; acc[2 * q + 1] = b.y;
    }
    {
        const u64 bx = bcast2(px), by = bcast2(py), bz = bcast2(pz);
        #pragma unroll
        for (int q = 0; q < 16; q++) {
            const ulonglong2 va = sW0[0][q];
            const ulonglong2 vb = sW0[1][q];
            const ulonglong2 vc = sW0[2][q];
            acc[2 * q]     = fma2(bx, va.x, acc[2 * q]);
            acc[2 * q + 1] = fma2(bx, va.y, acc[2 * q + 1]);
            acc[2 * q]     = fma2(by, vb.x, acc[2 * q]);
            acc[2 * q + 1] = fma2(by, vb.y, acc[2 * q + 1]);
            acc[2 * q]     = fma2(bz, vc.x, acc[2 * q]);
            acc[2 * q + 1] = fma2(bz, vc.y, acc[2 * q + 1]);
        }
    }
    #pragma unroll
    for (int lv = 0; lv < NLEV; lv++) {
        const int r = 3 + 2 * lv;
        const u64 bf0 = bcast2(e[lv].x), bf1 = bcast2(e[lv].y);
        #pragma unroll
        for (int q = 0; q < 16; q++) {
            const ulonglong2 va = sW0[r][q];
            const ulonglong2 vb = sW0[r + 1][q];
            acc[2 * q]     = fma2(bf0, va.x, acc[2 * q]);
            acc[2 * q + 1] = fma2(bf0, va.y, acc[2 * q + 1]);
            acc[2 * q]     = fma2(bf1, vb.x, acc[2 * q]);
            acc[2 * q + 1] = fma2(bf1, vb.y, acc[2 * q + 1]);
        }
    }

    float h[HIDDEN];
    #pragma unroll
    for (int j = 0; j < 32; j++) {
        float lo, hi; unpack2(acc[j], lo, hi);
        h[2 * j]     = softplus100(lo);
        h[2 * j + 1] = softplus100(hi);
    }

    // ---- layer 1 --------------------------------------------------------
    u64 acc1[32];
    #pragma unroll
    for (int q = 0; q < 16; q++) {
        const ulonglong2 b = sb1[q];
        acc1[2 * q] = b.x; acc1[2 * q + 1] = b.y;
    }
    #pragma unroll 4
    for (int i = 0; i < HIDDEN; i++) {
        const u64 hb = bcast2(h[i]);
        #pragma unroll
        for (int q = 0; q < 16; q++) {
            const ulonglong2 v = sW1[i][q];
            acc1[2 * q]     = fma2(hb, v.x, acc1[2 * q]);
            acc1[2 * q + 1] = fma2(hb, v.y, acc1[2 * q + 1]);
        }
    }
    float h1[HIDDEN];
    #pragma unroll
    for (int j = 0; j < 32; j++) {
        float lo, hi; unpack2(acc1[j], lo, hi);
        h1[2 * j]     = softplus100(lo);
        h1[2 * j + 1] = softplus100(hi);
    }

    // ---- layer 2 --------------------------------------------------------
    u64 acc2[8];
    #pragma unroll
    for (int q = 0; q < 4; q++) {
        const ulonglong2 b = sb2[q];
        acc2[2 * q] = b.x; acc2[2 * q + 1] = b.y;
    }
    #pragma unroll 8
    for (int i = 0; i < HIDDEN; i++) {
        const u64 hb = bcast2(h1[i]);
        #pragma unroll
        for (int q = 0; q < 4; q++) {
            const ulonglong2 v = sW2[i][q];
            acc2[2 * q]     = fma2(hb, v.x, acc2[2 * q]);
            acc2[2 * q + 1] = fma2(hb, v.y, acc2[2 * q + 1]);
        }
    }

    float o2[16];
    #pragma unroll
    for (int j = 0; j < 8; j++) unpack2(acc2[j], o2[2 * j], o2[2 * j + 1]);

    out[p] = o2[0];
    float* __restrict__ hout = out + n + (size_t)p * FEAT;
    #pragma unroll
    for (int j = 0; j < FEAT; j++) hout[j] = o2[j];
}

extern "C" void kernel_launch(void* const* d_in, const int* in_sizes, int n_in,
                              void* d_out, int out_size)
{
    const float* points = (const float*)d_in[0];
    const float* table  = (const float*)d_in[1];
    const float* V0 = (const float*)d_in[2];
    const float* g0 = (const float*)d_in[3];
    const float* b0 = (const float*)d_in[4];
    const float* V1 = (const float*)d_in[5];
    const float* g1 = (const float*)d_in[6];
    const float* b1 = (const float*)d_in[7];
    const float* V2 = (const float*)d_in[8];
    const float* g2 = (const float*)d_in[9];
    const float* b2 = (const float*)d_in[10];
    float* out = (float*)d_out;

    const int n = in_sizes[0] / 3;

    GridParams gp;
    const double scale = exp((log(2048.0) - log(16.0)) / 15.0);
    for (int lv = 0; lv < NLEV; lv++)
        gp.gs[lv] = (int)floor(16.0 * pow(scale, (double)lv)) + 1;

    prep_kernel<<<1, 64>>>(V0, g0, b0, V1, g1, b1, V2, g2, b2);
    pack_kernel<<<1, 256>>>();

    zero_hist_kernel<<<(NBUCK + 255) / 256, 256>>>();
    assign_kernel<<<(n + 255) / 256, 256>>>(points, n);
    scan_kernel<<<1, 256>>>();
    scatter_kernel<<<(n + 255) / 256, 256>>>(points, n);

    encode_kernel<<<(n + 255) / 256, 256>>>(table, n, gp);
    mlp_kernel<<<(n + 127) / 128, 128>>>(out, n);
}

// round 9
// speedup vs baseline: 1.1617x; 1.1617x over previous
#include <cuda_runtime.h>
#include <math.h>

#define NLEV   16
#define TSZ    524288
#define HIDDEN 64
#define FEAT   13
#define DIN    35

typedef unsigned long long u64;

__device__ __forceinline__ u64 pack2(float lo, float hi) {
    u64 r; asm("mov.b64 %0, {%1, %2};" : "=l"(r) : "f"(lo), "f"(hi)); return r;
}
__device__ __forceinline__ u64 bcast2(float v) { return pack2(v, v); }
__device__ __forceinline__ u64 fma2(u64 a, u64 b, u64 c) {
    u64 d; asm("fma.rn.f32x2 %0, %1, %2, %3;" : "=l"(d) : "l"(a), "l"(b), "l"(c)); return d;
}
__device__ __forceinline__ void unpack2(u64 v, float& lo, float& hi) {
    asm("mov.b64 {%0, %1}, %2;" : "=f"(lo), "=f"(hi) : "l"(v));
}

// ---------------------------------------------------------------------------
// Weight staging + value-packed ulonglong2 forms (native wide type, no punning)
// ---------------------------------------------------------------------------
__device__ float g_W0T[DIN][HIDDEN];
__device__ float g_W1T[HIDDEN][HIDDEN];
__device__ float g_W2T[HIDDEN][16];
__device__ float g_b0[HIDDEN];
__device__ float g_b1[HIDDEN];
__device__ float g_b2[16];

__device__ ulonglong2 g_W0p[DIN][16];
__device__ ulonglong2 g_W1p[HIDDEN][16];
__device__ ulonglong2 g_W2p[HIDDEN][4];
__device__ ulonglong2 g_b0p[16];
__device__ ulonglong2 g_b1p[16];
__device__ ulonglong2 g_b2p[4];

__global__ void prep_kernel(const float* __restrict__ V0, const float* __restrict__ g0, const float* __restrict__ b0,
                            const float* __restrict__ V1, const float* __restrict__ g1, const float* __restrict__ b1,
                            const float* __restrict__ V2, const float* __restrict__ g2, const float* __restrict__ b2)
{
    int o = threadIdx.x;
    if (o < HIDDEN) {
        float s = 0.f;
        for (int i = 0; i < DIN; i++) { float v = V0[o * DIN + i]; s += v * v; }
        float sc = g0[o] / sqrtf(s);
        for (int i = 0; i < DIN; i++) g_W0T[i][o] = V0[o * DIN + i] * sc;
        g_b0[o] = b0[o];

        s = 0.f;
        for (int i = 0; i < HIDDEN; i++) { float v = V1[o * HIDDEN + i]; s += v * v; }
        sc = g1[o] / sqrtf(s);
        for (int i = 0; i < HIDDEN; i++) g_W1T[i][o] = V1[o * HIDDEN + i] * sc;
        g_b1[o] = b1[o];
    }
    if (o < 16) {
        if (o < FEAT) {
            float s = 0.f;
            for (int i = 0; i < HIDDEN; i++) { float v = V2[o * HIDDEN + i]; s += v * v; }
            float sc = g2[o] / sqrtf(s);
            for (int i = 0; i < HIDDEN; i++) g_W2T[i][o] = V2[o * HIDDEN + i] * sc;
            g_b2[o] = b2[o];
        } else {
            for (int i = 0; i < HIDDEN; i++) g_W2T[i][o] = 0.f;
            g_b2[o] = 0.f;
        }
    }
}

__device__ __forceinline__ ulonglong2 pack4(const float* s) {
    ulonglong2 v;
    v.x = ((u64)__float_as_uint(s[1]) << 32) | (u64)__float_as_uint(s[0]);
    v.y = ((u64)__float_as_uint(s[3]) << 32) | (u64)__float_as_uint(s[2]);
    return v;
}

__global__ void pack_kernel()
{
    const int NW0 = DIN * 16, NW1 = HIDDEN * 16, NW2 = HIDDEN * 4;
    const int total = NW0 + NW1 + NW2 + 16 + 16 + 4;
    for (int e = threadIdx.x; e < total; e += blockDim.x) {
        int r = e;
        if (r < NW0) { (&g_W0p[0][0])[r] = pack4(&(&g_W0T[0][0])[4 * r]); continue; }
        r -= NW0;
        if (r < NW1) { (&g_W1p[0][0])[r] = pack4(&(&g_W1T[0][0])[4 * r]); continue; }
        r -= NW1;
        if (r < NW2) { (&g_W2p[0][0])[r] = pack4(&(&g_W2T[0][0])[4 * r]); continue; }
        r -= NW2;
        if (r < 16) { g_b0p[r] = pack4(&g_b0[4 * r]); continue; }
        r -= 16;
        if (r < 16) { g_b1p[r] = pack4(&g_b1[4 * r]); continue; }
        r -= 16;
        g_b2p[r] = pack4(&g_b2[4 * r]);
    }
}

struct GridParams { int gs[NLEV]; };

// Fast softplus(100z)/100.
// t = exp(-|x|) in (0,1]; log1p(t) ~= __logf(1+t). When t < 2^-24 the sum
// rounds to 1 and the correction (<1e-10 after /100) is far below the 1e-3
// tolerance; elsewhere MUFU lg2 gives ~1e-6 abs error on the /100 output.
__device__ __forceinline__ float softplus100(float z)
{
    float x = 100.f * z;
    float t = __expf(-fabsf(x));
    return (fmaxf(x, 0.f) + __logf(1.f + t)) * 0.01f;
}

// Corner order: c = i*4 + j*2 + k (matches reference OFFSETS loop nest).
__device__ __forceinline__ void level_setup(int gs, float ux, float uy, float uz,
                                            unsigned idxs[8], float& wx, float& wy, float& wz)
{
    const float gm1 = (float)(gs - 1);
    const float fx = ux * gm1, fy = uy * gm1, fz = uz * gm1;
    int ix = (int)floorf(fx); ix = min(max(ix, 0), gs - 2);
    int iy = (int)floorf(fy); iy = min(max(iy, 0), gs - 2);
    int iz = (int)floorf(fz); iz = min(max(iz, 0), gs - 2);
    wx = fx - (float)ix;
    wy = fy - (float)iy;
    wz = fz - (float)iz;

    if ((long long)gs * gs * gs <= (long long)TSZ) {
        const int g1 = gs, g2 = gs * gs;
        const int base = ix + g1 * iy + g2 * iz;
        idxs[0] = base;
        idxs[1] = base + g2;
        idxs[2] = base + g1;
        idxs[3] = base + g1 + g2;
        idxs[4] = base + 1;
        idxs[5] = base + 1 + g2;
        idxs[6] = base + 1 + g1;
        idxs[7] = base + 1 + g1 + g2;
    } else {
        const unsigned hx0 = (unsigned)ix,               hx1 = hx0 + 1u;
        const unsigned hy0 = (unsigned)iy * 2654435761u, hy1 = hy0 + 2654435761u;
        const unsigned hz0 = (unsigned)iz * 805459861u,  hz1 = hz0 + 805459861u;
        const unsigned M = (unsigned)(TSZ - 1);
        idxs[0] = (hx0 ^ hy0 ^ hz0) & M;
        idxs[1] = (hx0 ^ hy0 ^ hz1) & M;
        idxs[2] = (hx0 ^ hy1 ^ hz0) & M;
        idxs[3] = (hx0 ^ hy1 ^ hz1) & M;
        idxs[4] = (hx1 ^ hy0 ^ hz0) & M;
        idxs[5] = (hx1 ^ hy0 ^ hz1) & M;
        idxs[6] = (hx1 ^ hy1 ^ hz0) & M;
        idxs[7] = (hx1 ^ hy1 ^ hz1) & M;
    }
}

__global__ __launch_bounds__(128, 4)
void sdf_kernel(const float* __restrict__ points,
                const float* __restrict__ table,
                float* __restrict__ out,
                int n, GridParams gp)
{
    __shared__ ulonglong2 sW0[DIN][16];
    __shared__ ulonglong2 sW1[HIDDEN][16];
    __shared__ ulonglong2 sW2[HIDDEN][4];
    __shared__ ulonglong2 sb0[16];
    __shared__ ulonglong2 sb1[16];
    __shared__ ulonglong2 sb2[4];

    const int tid = threadIdx.x;
    for (int i = tid; i < DIN * 16;    i += 128) (&sW0[0][0])[i] = (&g_W0p[0][0])[i];
    for (int i = tid; i < HIDDEN * 16; i += 128) (&sW1[0][0])[i] = (&g_W1p[0][0])[i];
    for (int i = tid; i < HIDDEN * 4;  i += 128) (&sW2[0][0])[i] = (&g_W2p[0][0])[i];
    if (tid < 16) { sb0[tid] = g_b0p[tid]; sb1[tid] = g_b1p[tid]; }
    if (tid < 4)  { sb2[tid] = g_b2p[tid]; }
    __syncthreads();

    const int p = blockIdx.x * 128 + tid;
    if (p >= n) return;

    const float px = points[3 * p + 0];
    const float py = points[3 * p + 1];
    const float pz = points[3 * p + 2];
    const float ux = fminf(fmaxf((px + 1.f) * 0.5f, 0.f), 1.f);
    const float uy = fminf(fmaxf((py + 1.f) * 0.5f, 0.f), 1.f);
    const float uz = fminf(fmaxf((pz + 1.f) * 0.5f, 0.f), 1.f);

    // ---- layer 0: 32 packed accumulators, xyz contribution --------------
    u64 acc[32];
    #pragma unroll
    for (int q = 0; q < 16; q++) {
        const ulonglong2 b = sb0[q];
        acc[2 * q] = b.x; acc[2 * q + 1] = b.y;
    }
    {
        const u64 bx = bcast2(px), by = bcast2(py), bz = bcast2(pz);
        #pragma unroll
        for (int q = 0; q < 16; q++) {
            const ulonglong2 va = sW0[0][q];
            const ulonglong2 vb = sW0[1][q];
            const ulonglong2 vc = sW0[2][q];
            acc[2 * q]     = fma2(bx, va.x, acc[2 * q]);
            acc[2 * q + 1] = fma2(bx, va.y, acc[2 * q + 1]);
            acc[2 * q]     = fma2(by, vb.x, acc[2 * q]);
            acc[2 * q + 1] = fma2(by, vb.y, acc[2 * q + 1]);
            acc[2 * q]     = fma2(bz, vc.x, acc[2 * q]);
            acc[2 * q + 1] = fma2(bz, vc.y, acc[2 * q + 1]);
        }
    }

    const float2* __restrict__ tab = (const float2*)table;

    // ---- software-pipelined hashgrid levels -----------------------------
    float wxc, wyc, wzc;
    float2 fc[8];
    {
        unsigned idxs[8];
        level_setup(gp.gs[0], ux, uy, uz, idxs, wxc, wyc, wzc);
        #pragma unroll
        for (int c = 0; c < 8; c++) fc[c] = __ldg(&tab[idxs[c]]);
    }

    #pragma unroll 1
    for (int lv = 0; lv < NLEV; lv++) {
        float wxn = 0.f, wyn = 0.f, wzn = 0.f;
        float2 fn[8];
        #pragma unroll
        for (int c = 0; c < 8; c++) { fn[c].x = 0.f; fn[c].y = 0.f; }
        if (lv + 1 < NLEV) {
            unsigned idxs[8];
            level_setup(gp.gs[lv + 1], ux, uy, uz, idxs, wxn, wyn, wzn);
            const float2* __restrict__ tb = tab + (size_t)(lv + 1) * TSZ;
            #pragma unroll
            for (int c = 0; c < 8; c++) fn[c] = __ldg(&tb[idxs[c]]);
        }

        // consume current level: trilinear blend
        const float ox = 1.f - wxc, oy = 1.f - wyc, oz = 1.f - wzc;
        const float w0 = ox * oy * oz,   w1 = ox * oy * wzc;
        const float w2 = ox * wyc * oz,  w3 = ox * wyc * wzc;
        const float w4 = wxc * oy * oz,  w5 = wxc * oy * wzc;
        const float w6 = wxc * wyc * oz, w7 = wxc * wyc * wzc;
        const float f0 = fc[0].x * w0 + fc[1].x * w1 + fc[2].x * w2 + fc[3].x * w3
                       + fc[4].x * w4 + fc[5].x * w5 + fc[6].x * w6 + fc[7].x * w7;
        const float f1 = fc[0].y * w0 + fc[1].y * w1 + fc[2].y * w2 + fc[3].y * w3
                       + fc[4].y * w4 + fc[5].y * w5 + fc[6].y * w6 + fc[7].y * w7;

        const int r = 3 + 2 * lv;
        const u64 bf0 = bcast2(f0), bf1 = bcast2(f1);
        #pragma unroll
        for (int q = 0; q < 16; q++) {
            const ulonglong2 va = sW0[r][q];
            const ulonglong2 vb = sW0[r + 1][q];
            acc[2 * q]     = fma2(bf0, va.x, acc[2 * q]);
            acc[2 * q + 1] = fma2(bf0, va.y, acc[2 * q + 1]);
            acc[2 * q]     = fma2(bf1, vb.x, acc[2 * q]);
            acc[2 * q + 1] = fma2(bf1, vb.y, acc[2 * q + 1]);
        }

        wxc = wxn; wyc = wyn; wzc = wzn;
        #pragma unroll
        for (int c = 0; c < 8; c++) fc[c] = fn[c];
    }

    // softplus -> scalar h[64]
    float h[HIDDEN];
    #pragma unroll
    for (int j = 0; j < 32; j++) {
        float lo, hi; unpack2(acc[j], lo, hi);
        h[2 * j]     = softplus100(lo);
        h[2 * j + 1] = softplus100(hi);
    }

    // ---- layer 1 --------------------------------------------------------
    u64 acc1[32];
    #pragma unroll
    for (int q = 0; q < 16; q++) {
        const ulonglong2 b = sb1[q];
        acc1[2 * q] = b.x; acc1[2 * q + 1] = b.y;
    }
    #pragma unroll 4
    for (int i = 0; i < HIDDEN; i++) {
        const u64 hb = bcast2(h[i]);
        #pragma unroll
        for (int q = 0; q < 16; q++) {
            const ulonglong2 v = sW1[i][q];
            acc1[2 * q]     = fma2(hb, v.x, acc1[2 * q]);
            acc1[2 * q + 1] = fma2(hb, v.y, acc1[2 * q + 1]);
        }
    }
    float h1[HIDDEN];
    #pragma unroll
    for (int j = 0; j < 32; j++) {
        float lo, hi; unpack2(acc1[j], lo, hi);
        h1[2 * j]     = softplus100(lo);
        h1[2 * j + 1] = softplus100(hi);
    }

    // ---- layer 2 --------------------------------------------------------
    u64 acc2[8];
    #pragma unroll
    for (int q = 0; q < 4; q++) {
        const ulonglong2 b = sb2[q];
        acc2[2 * q] = b.x; acc2[2 * q + 1] = b.y;
    }
    #pragma unroll 8
    for (int i = 0; i < HIDDEN; i++) {
        const u64 hb = bcast2(h1[i]);
        #pragma unroll
        for (int q = 0; q < 4; q++) {
            const ulonglong2 v = sW2[i][q];
            acc2[2 * q]     = fma2(hb, v.x, acc2[2 * q]);
            acc2[2 * q + 1] = fma2(hb, v.y, acc2[2 * q + 1]);
        }
    }

    float o2[16];
    #pragma unroll
    for (int j = 0; j < 8; j++) unpack2(acc2[j], o2[2 * j], o2[2 * j + 1]);

    out[p] = o2[0];
    float* __restrict__ hout = out + n + (size_t)p * FEAT;
    #pragma unroll
    for (int j = 0; j < FEAT; j++) hout[j] = o2[j];
}

extern "C" void kernel_launch(void* const* d_in, const int* in_sizes, int n_in,
                              void* d_out, int out_size)
{
    const float* points = (const float*)d_in[0];
    const float* table  = (const float*)d_in[1];
    const float* V0 = (const float*)d_in[2];
    const float* g0 = (const float*)d_in[3];
    const float* b0 = (const float*)d_in[4];
    const float* V1 = (const float*)d_in[5];
    const float* g1 = (const float*)d_in[6];
    const float* b1 = (const float*)d_in[7];
    const float* V2 = (const float*)d_in[8];
    const float* g2 = (const float*)d_in[9];
    const float* b2 = (const float*)d_in[10];
    float* out = (float*)d_out;

    const int n = in_sizes[0] / 3;

    GridParams gp;
    const double scale = exp((log(2048.0) - log(16.0)) / 15.0);
    for (int lv = 0; lv < NLEV; lv++)
        gp.gs[lv] = (int)floor(16.0 * pow(scale, (double)lv)) + 1;

    prep_kernel<<<1, 64>>>(V0, g0, b0, V1, g1, b1, V2, g2, b2);
    pack_kernel<<<1, 256>>>();

    const int blocks = (n + 127) / 128;
    sdf_kernel<<<blocks, 128>>>(points, table, out, n, gp);
}

// round 10
// speedup vs baseline: 1.1818x; 1.0173x over previous
#include <cuda_runtime.h>
#include <math.h>

#define NLEV   16
#define TSZ    524288
#define HIDDEN 64
#define FEAT   13
#define DIN    35

typedef unsigned long long u64;

__device__ __forceinline__ u64 pack2(float lo, float hi) {
    u64 r; asm("mov.b64 %0, {%1, %2};" : "=l"(r) : "f"(lo), "f"(hi)); return r;
}
__device__ __forceinline__ u64 bcast2(float v) { return pack2(v, v); }
__device__ __forceinline__ u64 fma2(u64 a, u64 b, u64 c) {
    u64 d; asm("fma.rn.f32x2 %0, %1, %2, %3;" : "=l"(d) : "l"(a), "l"(b), "l"(c)); return d;
}
__device__ __forceinline__ void unpack2(u64 v, float& lo, float& hi) {
    asm("mov.b64 {%0, %1}, %2;" : "=f"(lo), "=f"(hi) : "l"(v));
}

// ---------------------------------------------------------------------------
// Weight staging + value-packed ulonglong2 forms (native wide type, no punning)
// ---------------------------------------------------------------------------
__device__ float g_W0T[DIN][HIDDEN];
__device__ float g_W1T[HIDDEN][HIDDEN];
__device__ float g_W2T[HIDDEN][16];
__device__ float g_b0[HIDDEN];
__device__ float g_b1[HIDDEN];
__device__ float g_b2[16];

__device__ ulonglong2 g_W0p[DIN][16];
__device__ ulonglong2 g_W1p[HIDDEN][16];
__device__ ulonglong2 g_W2p[HIDDEN][4];
__device__ ulonglong2 g_b0p[16];
__device__ ulonglong2 g_b1p[16];
__device__ ulonglong2 g_b2p[4];

__global__ void prep_kernel(const float* __restrict__ V0, const float* __restrict__ g0, const float* __restrict__ b0,
                            const float* __restrict__ V1, const float* __restrict__ g1, const float* __restrict__ b1,
                            const float* __restrict__ V2, const float* __restrict__ g2, const float* __restrict__ b2)
{
    int o = threadIdx.x;
    if (o < HIDDEN) {
        float s = 0.f;
        for (int i = 0; i < DIN; i++) { float v = V0[o * DIN + i]; s += v * v; }
        float sc = g0[o] / sqrtf(s);
        for (int i = 0; i < DIN; i++) g_W0T[i][o] = V0[o * DIN + i] * sc;
        g_b0[o] = b0[o];

        s = 0.f;
        for (int i = 0; i < HIDDEN; i++) { float v = V1[o * HIDDEN + i]; s += v * v; }
        sc = g1[o] / sqrtf(s);
        for (int i = 0; i < HIDDEN; i++) g_W1T[i][o] = V1[o * HIDDEN + i] * sc;
        g_b1[o] = b1[o];
    }
    if (o < 16) {
        if (o < FEAT) {
            float s = 0.f;
            for (int i = 0; i < HIDDEN; i++) { float v = V2[o * HIDDEN + i]; s += v * v; }
            float sc = g2[o] / sqrtf(s);
            for (int i = 0; i < HIDDEN; i++) g_W2T[i][o] = V2[o * HIDDEN + i] * sc;
            g_b2[o] = b2[o];
        } else {
            for (int i = 0; i < HIDDEN; i++) g_W2T[i][o] = 0.f;
            g_b2[o] = 0.f;
        }
    }
}

__device__ __forceinline__ ulonglong2 pack4(const float* s) {
    ulonglong2 v;
    v.x = ((u64)__float_as_uint(s[1]) << 32) | (u64)__float_as_uint(s[0]);
    v.y = ((u64)__float_as_uint(s[3]) << 32) | (u64)__float_as_uint(s[2]);
    return v;
}

__global__ void pack_kernel()
{
    const int NW0 = DIN * 16, NW1 = HIDDEN * 16, NW2 = HIDDEN * 4;
    const int total = NW0 + NW1 + NW2 + 16 + 16 + 4;
    for (int e = threadIdx.x; e < total; e += blockDim.x) {
        int r = e;
        if (r < NW0) { (&g_W0p[0][0])[r] = pack4(&(&g_W0T[0][0])[4 * r]); continue; }
        r -= NW0;
        if (r < NW1) { (&g_W1p[0][0])[r] = pack4(&(&g_W1T[0][0])[4 * r]); continue; }
        r -= NW1;
        if (r < NW2) { (&g_W2p[0][0])[r] = pack4(&(&g_W2T[0][0])[4 * r]); continue; }
        r -= NW2;
        if (r < 16) { g_b0p[r] = pack4(&g_b0[4 * r]); continue; }
        r -= 16;
        if (r < 16) { g_b1p[r] = pack4(&g_b1[4 * r]); continue; }
        r -= 16;
        g_b2p[r] = pack4(&g_b2[4 * r]);
    }
}

struct GridParams { int gs[NLEV]; };

// Fast softplus(100z)/100 (error audit in R8 — ~1e-6 abs on /100 output).
__device__ __forceinline__ float softplus100(float z)
{
    float x = 100.f * z;
    float t = __expf(-fabsf(x));
    return (fmaxf(x, 0.f) + __logf(1.f + t)) * 0.01f;
}

// Corner order: c = i*4 + j*2 + k (matches reference OFFSETS loop nest).
__device__ __forceinline__ void level_setup(int gs, float ux, float uy, float uz,
                                            unsigned idxs[8], float& wx, float& wy, float& wz)
{
    const float gm1 = (float)(gs - 1);
    const float fx = ux * gm1, fy = uy * gm1, fz = uz * gm1;
    int ix = (int)floorf(fx); ix = min(max(ix, 0), gs - 2);
    int iy = (int)floorf(fy); iy = min(max(iy, 0), gs - 2);
    int iz = (int)floorf(fz); iz = min(max(iz, 0), gs - 2);
    wx = fx - (float)ix;
    wy = fy - (float)iy;
    wz = fz - (float)iz;

    if ((long long)gs * gs * gs <= (long long)TSZ) {
        const int g1 = gs, g2 = gs * gs;
        const int base = ix + g1 * iy + g2 * iz;
        idxs[0] = base;
        idxs[1] = base + g2;
        idxs[2] = base + g1;
        idxs[3] = base + g1 + g2;
        idxs[4] = base + 1;
        idxs[5] = base + 1 + g2;
        idxs[6] = base + 1 + g1;
        idxs[7] = base + 1 + g1 + g2;
    } else {
        const unsigned hx0 = (unsigned)ix,               hx1 = hx0 + 1u;
        const unsigned hy0 = (unsigned)iy * 2654435761u, hy1 = hy0 + 2654435761u;
        const unsigned hz0 = (unsigned)iz * 805459861u,  hz1 = hz0 + 805459861u;
        const unsigned M = (unsigned)(TSZ - 1);
        idxs[0] = (hx0 ^ hy0 ^ hz0) & M;
        idxs[1] = (hx0 ^ hy0 ^ hz1) & M;
        idxs[2] = (hx0 ^ hy1 ^ hz0) & M;
        idxs[3] = (hx0 ^ hy1 ^ hz1) & M;
        idxs[4] = (hx1 ^ hy0 ^ hz0) & M;
        idxs[5] = (hx1 ^ hy0 ^ hz1) & M;
        idxs[6] = (hx1 ^ hy1 ^ hz0) & M;
        idxs[7] = (hx1 ^ hy1 ^ hz1) & M;
    }
}

__global__ __launch_bounds__(128, 5)
void sdf_kernel(const float* __restrict__ points,
                const float* __restrict__ table,
                float* __restrict__ out,
                int n, GridParams gp)
{
    __shared__ ulonglong2 sW0[DIN][16];
    __shared__ ulonglong2 sW1[HIDDEN][16];
    __shared__ ulonglong2 sW2[HIDDEN][4];
    __shared__ ulonglong2 sb0[16];
    __shared__ ulonglong2 sb1[16];
    __shared__ ulonglong2 sb2[4];

    const int tid = threadIdx.x;
    for (int i = tid; i < DIN * 16;    i += 128) (&sW0[0][0])[i] = (&g_W0p[0][0])[i];
    for (int i = tid; i < HIDDEN * 16; i += 128) (&sW1[0][0])[i] = (&g_W1p[0][0])[i];
    for (int i = tid; i < HIDDEN * 4;  i += 128) (&sW2[0][0])[i] = (&g_W2p[0][0])[i];
    if (tid < 16) { sb0[tid] = g_b0p[tid]; sb1[tid] = g_b1p[tid]; }
    if (tid < 4)  { sb2[tid] = g_b2p[tid]; }
    __syncthreads();

    const int p = blockIdx.x * 128 + tid;
    if (p >= n) return;

    const float px = points[3 * p + 0];
    const float py = points[3 * p + 1];
    const float pz = points[3 * p + 2];
    const float ux = fminf(fmaxf((px + 1.f) * 0.5f, 0.f), 1.f);
    const float uy = fminf(fmaxf((py + 1.f) * 0.5f, 0.f), 1.f);
    const float uz = fminf(fmaxf((pz + 1.f) * 0.5f, 0.f), 1.f);

    const float2* __restrict__ tab = (const float2*)table;

    // ---- gather phase: per-level features into scalar regs --------------
    float enc[2 * NLEV];
    #pragma unroll
    for (int lv = 0; lv < NLEV; lv++) {
        unsigned idxs[8];
        float wx, wy, wz;
        level_setup(gp.gs[lv], ux, uy, uz, idxs, wx, wy, wz);
        const float2* __restrict__ tb = tab + (size_t)lv * TSZ;
        float2 f[8];
        #pragma unroll
        for (int c = 0; c < 8; c++) f[c] = __ldg(&tb[idxs[c]]);

        const float ox = 1.f - wx, oy = 1.f - wy, oz = 1.f - wz;
        const float w0 = ox * oy * oz,  w1 = ox * oy * wz;
        const float w2 = ox * wy * oz,  w3 = ox * wy * wz;
        const float w4 = wx * oy * oz,  w5 = wx * oy * wz;
        const float w6 = wx * wy * oz,  w7 = wx * wy * wz;
        enc[2 * lv]     = f[0].x * w0 + f[1].x * w1 + f[2].x * w2 + f[3].x * w3
                        + f[4].x * w4 + f[5].x * w5 + f[6].x * w6 + f[7].x * w7;
        enc[2 * lv + 1] = f[0].y * w0 + f[1].y * w1 + f[2].y * w2 + f[3].y * w3
                        + f[4].y * w4 + f[5].y * w5 + f[6].y * w6 + f[7].y * w7;
    }

    // ---- layer 0: two output halves (16 u64 acc live at a time) ---------
    float h[HIDDEN];
    #pragma unroll
    for (int half = 0; half < 2; half++) {
        u64 acc[16];
        #pragma unroll
        for (int q = 0; q < 8; q++) {
            const ulonglong2 b = sb0[8 * half + q];
            acc[2 * q] = b.x; acc[2 * q + 1] = b.y;
        }
        const u64 bx = bcast2(px), by = bcast2(py), bz = bcast2(pz);
        #pragma unroll
        for (int q = 0; q < 8; q++) {
            const ulonglong2 va = sW0[0][8 * half + q];
            const ulonglong2 vb = sW0[1][8 * half + q];
            const ulonglong2 vc = sW0[2][8 * half + q];
            acc[2 * q]     = fma2(bx, va.x, acc[2 * q]);
            acc[2 * q + 1] = fma2(bx, va.y, acc[2 * q + 1]);
            acc[2 * q]     = fma2(by, vb.x, acc[2 * q]);
            acc[2 * q + 1] = fma2(by, vb.y, acc[2 * q + 1]);
            acc[2 * q]     = fma2(bz, vc.x, acc[2 * q]);
            acc[2 * q + 1] = fma2(bz, vc.y, acc[2 * q + 1]);
        }
        #pragma unroll
        for (int lv = 0; lv < NLEV; lv++) {
            const int r = 3 + 2 * lv;
            const u64 bf0 = bcast2(enc[2 * lv]), bf1 = bcast2(enc[2 * lv + 1]);
            #pragma unroll
            for (int q = 0; q < 8; q++) {
                const ulonglong2 va = sW0[r][8 * half + q];
                const ulonglong2 vb = sW0[r + 1][8 * half + q];
                acc[2 * q]     = fma2(bf0, va.x, acc[2 * q]);
                acc[2 * q + 1] = fma2(bf0, va.y, acc[2 * q + 1]);
                acc[2 * q]     = fma2(bf1, vb.x, acc[2 * q]);
                acc[2 * q + 1] = fma2(bf1, vb.y, acc[2 * q + 1]);
            }
        }
        #pragma unroll
        for (int j = 0; j < 16; j++) {
            float lo, hi; unpack2(acc[j], lo, hi);
            h[32 * half + 2 * j]     = softplus100(lo);
            h[32 * half + 2 * j + 1] = softplus100(hi);
        }
    }

    // ---- layer 1: two output halves -------------------------------------
    float h1[HIDDEN];
    #pragma unroll
    for (int half = 0; half < 2; half++) {
        u64 acc1[16];
        #pragma unroll
        for (int q = 0; q < 8; q++) {
            const ulonglong2 b = sb1[8 * half + q];
            acc1[2 * q] = b.x; acc1[2 * q + 1] = b.y;
        }
        #pragma unroll 8
        for (int i = 0; i < HIDDEN; i++) {
            const u64 hb = bcast2(h[i]);
            #pragma unroll
            for (int q = 0; q < 8; q++) {
                const ulonglong2 v = sW1[i][8 * half + q];
                acc1[2 * q]     = fma2(hb, v.x, acc1[2 * q]);
                acc1[2 * q + 1] = fma2(hb, v.y, acc1[2 * q + 1]);
            }
        }
        #pragma unroll
        for (int j = 0; j < 16; j++) {
            float lo, hi; unpack2(acc1[j], lo, hi);
            h1[32 * half + 2 * j]     = softplus100(lo);
            h1[32 * half + 2 * j + 1] = softplus100(hi);
        }
    }

    // ---- layer 2 ---------------------------------------------------------
    u64 acc2[8];
    #pragma unroll
    for (int q = 0; q < 4; q++) {
        const ulonglong2 b = sb2[q];
        acc2[2 * q] = b.x; acc2[2 * q + 1] = b.y;
    }
    #pragma unroll 8
    for (int i = 0; i < HIDDEN; i++) {
        const u64 hb = bcast2(h1[i]);
        #pragma unroll
        for (int q = 0; q < 4; q++) {
            const ulonglong2 v = sW2[i][q];
            acc2[2 * q]     = fma2(hb, v.x, acc2[2 * q]);
            acc2[2 * q + 1] = fma2(hb, v.y, acc2[2 * q + 1]);
        }
    }

    float o2[16];
    #pragma unroll
    for (int j = 0; j < 8; j++) unpack2(acc2[j], o2[2 * j], o2[2 * j + 1]);

    out[p] = o2[0];
    float* __restrict__ hout = out + n + (size_t)p * FEAT;
    #pragma unroll
    for (int j = 0; j < FEAT; j++) hout[j] = o2[j];
}

extern "C" void kernel_launch(void* const* d_in, const int* in_sizes, int n_in,
                              void* d_out, int out_size)
{
    const float* points = (const float*)d_in[0];
    const float* table  = (const float*)d_in[1];
    const float* V0 = (const float*)d_in[2];
    const float* g0 = (const float*)d_in[3];
    const float* b0 = (const float*)d_in[4];
    const float* V1 = (const float*)d_in[5];
    const float* g1 = (const float*)d_in[6];
    const float* b1 = (const float*)d_in[7];
    const float* V2 = (const float*)d_in[8];
    const float* g2 = (const float*)d_in[9];
    const float* b2 = (const float*)d_in[10];
    float* out = (float*)d_out;

    const int n = in_sizes[0] / 3;

    GridParams gp;
    const double scale = exp((log(2048.0) - log(16.0)) / 15.0);
    for (int lv = 0; lv < NLEV; lv++)
        gp.gs[lv] = (int)floor(16.0 * pow(scale, (double)lv)) + 1;

    prep_kernel<<<1, 64>>>(V0, g0, b0, V1, g1, b1, V2, g2, b2);
    pack_kernel<<<1, 256>>>();

    const int blocks = (n + 127) / 128;
    sdf_kernel<<<blocks, 128>>>(points, table, out, n, gp);
}